// round 8
// baseline (speedup 1.0000x reference)
#include <cuda_runtime.h>
#include <math.h>
#include <stdint.h>

static constexpr int Bb    = 8;
static constexpr int PLANE = 256 * 1024;

// Scratch (static device globals; allocation-free per harness rules)
// packed fp16x2 activations (pairs along channel unless noted)
__device__ uint32_t g_qp [8 * 128 * 1024];  // [b][c2][s]
__device__ uint32_t g_kpx[8 * 128 * 1024];  // [b][c2][s]
__device__ uint32_t g_Qp [8 * 128 * 1024];  // [b][c2][s]
__device__ uint32_t g_Kp [8 * 1024 * 128];  // [b][s][c2]  (LDSM-friendly)
__device__ uint32_t g_Vp [8 * 256 * 512];   // [b][d][s2]  (pairs along s)
__device__ uint32_t g_Osp[8 * 128 * 1024];  // [b][c2][s]
__device__ float    g_ys [8 * 256 * 1024];  // Wo output (small grid), fp32
__device__ uint32_t g_Wk [4 * 128 * 256];   // weights k-major packed: [w][c2][o]

// ---------------------------------------------------------------------------
__device__ __forceinline__ uint32_t pk(float lo, float hi) {
    uint32_t r;
    asm("cvt.rn.f16x2.f32 %0, %1, %2;" : "=r"(r) : "f"(hi), "f"(lo));
    return r;
}
__device__ __forceinline__ uint32_t ex2h2(uint32_t x) {
    uint32_t r;
    asm("ex2.approx.f16x2 %0, %1;" : "=r"(r) : "r"(x));
    return r;
}
__device__ __forceinline__ void mma_f16(float* d, const uint32_t* a,
                                        uint32_t b0, uint32_t b1) {
    asm volatile(
        "mma.sync.aligned.m16n8k16.row.col.f32.f16.f16.f32 "
        "{%0,%1,%2,%3}, {%4,%5,%6,%7}, {%8,%9}, {%0,%1,%2,%3};"
        : "+f"(d[0]), "+f"(d[1]), "+f"(d[2]), "+f"(d[3])
        : "r"(a[0]), "r"(a[1]), "r"(a[2]), "r"(a[3]), "r"(b0), "r"(b1));
}
__device__ __forceinline__ void ldsm4(uint32_t& r0, uint32_t& r1,
                                      uint32_t& r2, uint32_t& r3, uint32_t addr) {
    asm volatile("ldmatrix.sync.aligned.m8n8.x4.shared.b16 {%0,%1,%2,%3}, [%4];"
                 : "=r"(r0), "=r"(r1), "=r"(r2), "=r"(r3) : "r"(addr));
}
__device__ __forceinline__ void cpa16(uint32_t dst, const void* src) {
    asm volatile("cp.async.cg.shared.global [%0], [%1], 16;" :: "r"(dst), "l"(src));
}
__device__ __forceinline__ void cp_commit() { asm volatile("cp.async.commit_group;"); }
__device__ __forceinline__ void cp_wait1()  { asm volatile("cp.async.wait_group 1;"); }
__device__ __forceinline__ void cp_wait0()  { asm volatile("cp.async.wait_group 0;"); }
__device__ __forceinline__ uint32_t smem_u32(const void* p) {
    return (uint32_t)__cvta_generic_to_shared(p);
}

// ---------------------------------------------------------------------------
// Merged prep: blocks [0,512) pack weights; blocks [512,1536) avg-pool.
// Wq gets scale*log2(e) folded in.
// ---------------------------------------------------------------------------
__global__ __launch_bounds__(256) void prep_pool(const float* __restrict__ Wq,
                                                 const float* __restrict__ Wk_,
                                                 const float* __restrict__ Wv,
                                                 const float* __restrict__ Wo,
                                                 const float* __restrict__ q,
                                                 const float* __restrict__ kv)
{
    if (blockIdx.x < 512) {
        int idx = blockIdx.x * 256 + threadIdx.x;   // 131072 total
        int w  = idx >> 15;
        int c2 = (idx >> 8) & 127;
        int o  = idx & 255;
        const float* W = (w == 0) ? Wq : (w == 1) ? Wk_ : (w == 2) ? Wv : Wo;
        float2 v = *(const float2*)(W + o * 256 + 2 * c2);
        if (w == 0) {
            const float qs = 0.17677669529663687f * 1.4426950408889634f;
            v.x *= qs; v.y *= qs;
        }
        g_Wk[(w * 128 + c2) * 256 + o] = pk(v.x, v.y);
        return;
    }
    int idx = (blockIdx.x - 512) * 256 + threadIdx.x;   // 262144 total
    int s4 = idx & 255;
    int c2 = (idx >> 8) & 127;
    int b  = idx >> 15;
    int s  = s4 << 2;
    int px = s & 31, py = s >> 5;

    long base0 = (((long)(b * 256 + 2 * c2)) * 64 + 2 * py) * 64 + 2 * px;
    long base1 = base0 + 4096;  // next channel

    uint32_t outq[4], outk[4];
#pragma unroll
    for (int tsel = 0; tsel < 2; tsel++) {
        const float* src = tsel ? kv : q;
        float4 a00 = *(const float4*)(src + base0);
        float4 a01 = *(const float4*)(src + base0 + 4);
        float4 a10 = *(const float4*)(src + base0 + 64);
        float4 a11 = *(const float4*)(src + base0 + 68);
        float4 b00 = *(const float4*)(src + base1);
        float4 b01 = *(const float4*)(src + base1 + 4);
        float4 b10 = *(const float4*)(src + base1 + 64);
        float4 b11 = *(const float4*)(src + base1 + 68);
        float pA0 = 0.25f * (a00.x + a00.y + a10.x + a10.y);
        float pA1 = 0.25f * (a00.z + a00.w + a10.z + a10.w);
        float pA2 = 0.25f * (a01.x + a01.y + a11.x + a11.y);
        float pA3 = 0.25f * (a01.z + a01.w + a11.z + a11.w);
        float pB0 = 0.25f * (b00.x + b00.y + b10.x + b10.y);
        float pB1 = 0.25f * (b00.z + b00.w + b10.z + b10.w);
        float pB2 = 0.25f * (b01.x + b01.y + b11.x + b11.y);
        float pB3 = 0.25f * (b01.z + b01.w + b11.z + b11.w);
        uint32_t* dst = tsel ? outk : outq;
        dst[0] = pk(pA0, pB0); dst[1] = pk(pA1, pB1);
        dst[2] = pk(pA2, pB2); dst[3] = pk(pA3, pB3);
    }
    long off = ((long)(b * 128 + c2) << 10) + s;
    *(uint4*)&g_qp [off] = make_uint4(outq[0], outq[1], outq[2], outq[3]);
    *(uint4*)&g_kpx[off] = make_uint4(outk[0], outk[1], outk[2], outk[3]);
}

// ---------------------------------------------------------------------------
// fp16 GEMM body, templated n-tile NT (128 or 64): Y = W @ X tile,
// block 128 x NT, 2-stage cp.async.  acc[2][NT/16][4].
// ---------------------------------------------------------------------------
template <int NT>
__device__ __forceinline__ void gemm_body_t(const uint32_t* __restrict__ Wk,
                                            const uint32_t* __restrict__ X,
                                            uint32_t Ws[2][16][136],
                                            uint32_t Xs[2][16][NT + 8],
                                            float acc[2][NT / 16][4],
                                            int m0, int n0)
{
    constexpr int NI = NT / 16;
    const int tid = threadIdx.x;
    const int w = tid >> 5, t = tid & 31, g = t >> 2, c = t & 3;
    const int wm = (w >> 1) * 32, wn = (w & 1) * (NT / 2);

#pragma unroll
    for (int mi = 0; mi < 2; mi++)
#pragma unroll
        for (int ni = 0; ni < NI; ni++)
#pragma unroll
            for (int r = 0; r < 4; r++) acc[mi][ni][r] = 0.f;

    constexpr int CPR = NT / 4;            // 16B chunks per X row
    constexpr int XIT = (16 * CPR) / 256;  // staging iterations for X

    auto stage = [&](int s, int kb) {
        uint32_t wb = smem_u32(&Ws[s][0][0]);
        uint32_t xb = smem_u32(&Xs[s][0][0]);
#pragma unroll
        for (int i = 0; i < 2; i++) {
            int id = tid + (i << 8);
            int r = id >> 5, col = (id & 31) << 2;
            cpa16(wb + (uint32_t)((r * 136 + col) << 2),
                  Wk + (kb * 16 + r) * 256 + m0 + col);
        }
#pragma unroll
        for (int i = 0; i < XIT; i++) {
            int id = tid + (i << 8);
            int r = id / CPR, col = (id % CPR) << 2;
            cpa16(xb + (uint32_t)((r * (NT + 8) + col) << 2),
                  X + (kb * 16 + r) * 1024 + n0 + col);
        }
        cp_commit();
    };

    stage(0, 0);
    for (int kb = 0; kb < 8; kb++) {
        int cur = kb & 1;
        if (kb < 7) { stage(1 - cur, kb + 1); cp_wait1(); }
        else        { cp_wait0(); }
        __syncthreads();
#pragma unroll
        for (int ks = 0; ks < 2; ks++) {
            uint32_t a[2][4];
#pragma unroll
            for (int mi = 0; mi < 2; mi++) {
                int mb = wm + mi * 16;
                a[mi][0] = Ws[cur][8 * ks + c][mb + g];
                a[mi][1] = Ws[cur][8 * ks + c][mb + g + 8];
                a[mi][2] = Ws[cur][8 * ks + c + 4][mb + g];
                a[mi][3] = Ws[cur][8 * ks + c + 4][mb + g + 8];
            }
#pragma unroll
            for (int ni = 0; ni < NI; ni++) {
                uint32_t b0 = Xs[cur][8 * ks + c][wn + ni * 8 + g];
                uint32_t b1 = Xs[cur][8 * ks + c + 4][wn + ni * 8 + g];
                mma_f16(acc[0][ni], a[0], b0, b1);
                mma_f16(acc[1][ni], a[1], b0, b1);
            }
        }
        __syncthreads();
    }
}

// QKV epilogues: Q -> [c2][s]; K -> [s][c2] (LDSM layout); V -> [d][s2]
__global__ __launch_bounds__(256, 2) void gemm_qkv()
{
    __shared__ uint32_t Ws[2][16][136];
    __shared__ uint32_t Xs[2][16][136];
    int z = blockIdx.z;
    int b = z / 3, w3 = z - 3 * b;
    const uint32_t* Wk = g_Wk + w3 * 128 * 256;
    const uint32_t* X  = ((w3 == 0) ? g_qp : g_kpx) + b * 128 * 1024;
    int m0 = blockIdx.y * 128, n0 = blockIdx.x * 128;

    float acc[2][8][4];
    gemm_body_t<128>(Wk, X, Ws, Xs, acc, m0, n0);

    const int tid = threadIdx.x;
    const int w = tid >> 5, t = tid & 31, g = t >> 2, c = t & 3;
    const int wm = (w >> 1) * 32, wn = (w & 1) * 64;

    if (w3 < 2) {
        bool even = (g & 1) == 0;
#pragma unroll
        for (int mi = 0; mi < 2; mi++) {
            int base = m0 + wm + mi * 16;
#pragma unroll
            for (int ni = 0; ni < 8; ni++) {
                float p0 = __shfl_xor_sync(0xffffffffu, acc[mi][ni][0], 4);
                float p1 = __shfl_xor_sync(0xffffffffu, acc[mi][ni][1], 4);
                float p2 = __shfl_xor_sync(0xffffffffu, acc[mi][ni][2], 4);
                float p3 = __shfl_xor_sync(0xffffffffu, acc[mi][ni][3], 4);
                uint32_t w0, w1; int d2;
                if (even) {
                    w0 = pk(acc[mi][ni][0], p0);
                    w1 = pk(acc[mi][ni][1], p1);
                    d2 = (base + g) >> 1;
                } else {
                    w0 = pk(p2, acc[mi][ni][2]);
                    w1 = pk(p3, acc[mi][ni][3]);
                    d2 = (base + 7 + g) >> 1;
                }
                int col = n0 + wn + ni * 8 + 2 * c;
                if (w3 == 0) {
                    uint32_t* Yp = g_Qp + b * 128 * 1024;
                    *(uint2*)&Yp[(long)d2 * 1024 + col] = make_uint2(w0, w1);
                } else {
                    uint32_t* Kp = g_Kp + (long)b * 1024 * 128;
                    Kp[(long)col * 128 + d2]       = w0;
                    Kp[(long)(col + 1) * 128 + d2] = w1;
                }
            }
        }
    } else {
        uint32_t* Vp = g_Vp + b * 256 * 512;
#pragma unroll
        for (int mi = 0; mi < 2; mi++) {
            int base = m0 + wm + mi * 16;
#pragma unroll
            for (int ni = 0; ni < 8; ni++) {
                int s2 = ((n0 + wn) >> 1) + ni * 4 + c;
                Vp[(long)(base + g) * 512 + s2]     = pk(acc[mi][ni][0], acc[mi][ni][1]);
                Vp[(long)(base + g + 8) * 512 + s2] = pk(acc[mi][ni][2], acc[mi][ni][3]);
            }
        }
    }
}

// Wo GEMM: n-tile 64 -> grid 256 blocks (fills the chip; 2 CTAs/SM)
__global__ __launch_bounds__(256) void gemm_o()
{
    __shared__ uint32_t Ws[2][16][136];
    __shared__ uint32_t Xs[2][16][72];
    int b = blockIdx.z;
    int m0 = blockIdx.y * 128, n0 = blockIdx.x * 64;
    float acc[2][4][4];
    gemm_body_t<64>(g_Wk + 3 * 128 * 256, g_Osp + b * 128 * 1024, Ws, Xs, acc, m0, n0);

    const int tid = threadIdx.x;
    const int w = tid >> 5, t = tid & 31, g = t >> 2, c = t & 3;
    const int wm = (w >> 1) * 32, wn = (w & 1) * 32;
    float* Y = g_ys + (long)b * PLANE;
#pragma unroll
    for (int mi = 0; mi < 2; mi++) {
        int r = m0 + wm + mi * 16 + g;
#pragma unroll
        for (int ni = 0; ni < 4; ni++) {
            int col = n0 + wn + ni * 8 + 2 * c;
            *(float2*)(Y + (long)r * 1024 + col) =
                make_float2(acc[mi][ni][0], acc[mi][ni][1]);
            *(float2*)(Y + (long)(r + 8) * 1024 + col) =
                make_float2(acc[mi][ni][2], acc[mi][ni][3]);
        }
    }
}

// ---------------------------------------------------------------------------
// Flash attention, fp16 mma, 2-stage cp.async, LDSM fragments,
// shift-free base-2 softmax with paired f16x2 exp; l via ones-MMA.
// ---------------------------------------------------------------------------
__global__ __launch_bounds__(256, 3) void attn_kernel()
{
    __shared__ uint32_t Ks[2][64][20];   // [key][d2] (16 words used, pad 20)
    __shared__ uint32_t Vs[2][32][36];   // [d][s2]

    const int b  = blockIdx.z;
    const int h  = blockIdx.y;
    const int qt = blockIdx.x;
    const int tid = threadIdx.x;
    const int w = tid >> 5, t = tid & 31, g = t >> 2, c = t & 3;
    const int q0 = qt * 128 + w * 16;
    const uint32_t ONESx2 = 0x3C003C00u;   // fp16 {1.0, 1.0}

    const uint32_t* Qp = g_Qp + (long)(b * 128 + h * 16) * 1024;
    const uint32_t* Kp = g_Kp + (long)b * 1024 * 128;    // [s][c2]
    const uint32_t* Vp = g_Vp + (long)(b * 256 + h * 32) * 512;

    // Q fragments (scale*log2e folded into Wq)
    uint32_t qa[2][4];
#pragma unroll
    for (int ks = 0; ks < 2; ks++) {
        qa[ks][0] = Qp[(8 * ks + c) * 1024 + q0 + g];
        qa[ks][1] = Qp[(8 * ks + c) * 1024 + q0 + g + 8];
        qa[ks][2] = Qp[(8 * ks + c + 4) * 1024 + q0 + g];
        qa[ks][3] = Qp[(8 * ks + c + 4) * 1024 + q0 + g + 8];
    }

    float lC[4] = {0.f, 0.f, 0.f, 0.f};   // row-sum accumulator (ones-MMA)
    float o[4][4];
#pragma unroll
    for (int ni = 0; ni < 4; ni++)
#pragma unroll
        for (int r = 0; r < 4; r++) o[ni][r] = 0.f;

    // staging indices
    const int sk_key = tid >> 2, sk_j = (tid & 3) << 2;  // K: 64 keys x 4 chunks
    const int vr = tid >> 3, vc = (tid & 7) << 2;        // V: 32 d x 4 chunks
    const int kcol = h * 16;

    const int lm8 = ((t >> 4) & 1) * 8 + (t & 7);
    const int lc4 = ((t >> 3) & 1) * 4;

    auto stage = [&](int s, int k0) {
        cpa16(smem_u32(&Ks[s][sk_key][sk_j]),
              Kp + (long)(k0 + sk_key) * 128 + kcol + sk_j);
        cpa16(smem_u32(&Vs[s][vr][vc]),
              Vp + vr * 512 + (k0 >> 1) + vc);
        cp_commit();
    };

    stage(0, 0);
    for (int it = 0; it < 16; it++) {
        int cur = it & 1;
        if (it < 15) { stage(1 - cur, (it + 1) * 64); cp_wait1(); }
        else         { cp_wait0(); }
        __syncthreads();

        // S = Q K^T (base-2 logits), K b-frags via ldmatrix
        float S[8][4];
#pragma unroll
        for (int ni = 0; ni < 8; ni++)
#pragma unroll
            for (int r = 0; r < 4; r++) S[ni][r] = 0.f;
#pragma unroll
        for (int ks = 0; ks < 2; ks++) {
#pragma unroll
            for (int np = 0; np < 4; np++) {
                uint32_t b0, b1, b2, b3;
                ldsm4(b0, b1, b2, b3,
                      smem_u32(&Ks[cur][np * 16 + lm8][ks * 8 + lc4]));
                mma_f16(S[2 * np],     qa[ks], b0, b1);
                mma_f16(S[2 * np + 1], qa[ks], b2, b3);
            }
        }

        // pack logits to f16x2, paired exp2 -> P fragments directly
        uint32_t P[8][2];
#pragma unroll
        for (int ni = 0; ni < 8; ni++) {
            P[ni][0] = ex2h2(pk(S[ni][0], S[ni][1]));
            P[ni][1] = ex2h2(pk(S[ni][2], S[ni][3]));
        }

        // P.V + l row-sum via ones-MMA
#pragma unroll
        for (int ks4 = 0; ks4 < 4; ks4++) {
            uint32_t pa[4];
            pa[0] = P[2 * ks4][0];
            pa[1] = P[2 * ks4][1];
            pa[2] = P[2 * ks4 + 1][0];
            pa[3] = P[2 * ks4 + 1][1];
            mma_f16(lC, pa, ONESx2, ONESx2);
#pragma unroll
            for (int nip = 0; nip < 2; nip++) {
                uint32_t v0, v1, v2, v3;
                ldsm4(v0, v1, v2, v3,
                      smem_u32(&Vs[cur][nip * 16 + lm8][ks4 * 8 + lc4]));
                mma_f16(o[2 * nip],     pa, v0, v1);
                mma_f16(o[2 * nip + 1], pa, v2, v3);
            }
        }
        __syncthreads();
    }

    // lC[0] = full row sum (row g), lC[2] = row g+8; no shfl needed
    float inv0 = 1.f / lC[0], inv1 = 1.f / lC[2];
    uint32_t* Osp = g_Osp + (long)(b * 128 + h * 16) * 1024;
#pragma unroll
    for (int ni = 0; ni < 4; ni++) {
        int d2 = 4 * ni + c;
        Osp[(long)d2 * 1024 + q0 + g]     = pk(o[ni][0] * inv0, o[ni][1] * inv0);
        Osp[(long)d2 * 1024 + q0 + g + 8] = pk(o[ni][2] * inv1, o[ni][3] * inv1);
    }
}

// ---------------------------------------------------------------------------
// Final: bilinear 2x upsample + residual + BatchNorm(eval); 4 px/thread
// ---------------------------------------------------------------------------
__global__ __launch_bounds__(256) void final_kernel(const float* __restrict__ query,
                                                    const float* __restrict__ gamma,
                                                    const float* __restrict__ beta,
                                                    const float* __restrict__ mean,
                                                    const float* __restrict__ var,
                                                    float* __restrict__ out)
{
    int idx = blockIdx.x * 256 + threadIdx.x;       // 2097152 total
    int x4 = (idx & 15) << 2;
    int y  = (idx >> 4) & 63;
    int bc = idx >> 10;
    int c  = bc & 255;

    const float* ys = g_ys + (long)bc * 1024;
    int jy = y >> 1;
    int oy = (y & 1) ? min(jy + 1, 31) : max(jy - 1, 0);
    const float* r0 = ys + jy * 32;
    const float* r1 = ys + oy * 32;

    float gg = gamma[c] * rsqrtf(var[c] + 1e-5f);
    float bb = beta[c] - mean[c] * gg;

    long qoff = ((long)bc * 64 + y) * 64 + x4;
    float4 qv = *(const float4*)(query + qoff);
    float qq[4] = {qv.x, qv.y, qv.z, qv.w};
    float res[4];
#pragma unroll
    for (int p = 0; p < 4; p++) {
        int x = x4 + p;
        int jx = x >> 1;
        int ox = (x & 1) ? min(jx + 1, 31) : max(jx - 1, 0);
        float v = 0.75f * (0.75f * r0[jx] + 0.25f * r0[ox])
                + 0.25f * (0.75f * r1[jx] + 0.25f * r1[ox]);
        res[p] = (v + qq[p]) * gg + bb;
    }
    *(float4*)(out + qoff) = make_float4(res[0], res[1], res[2], res[3]);
}

// ---------------------------------------------------------------------------
extern "C" void kernel_launch(void* const* d_in, const int* in_sizes, int n_in,
                              void* d_out, int out_size)
{
    (void)in_sizes; (void)n_in; (void)out_size;
    const float* query = (const float*)d_in[0];
    const float* kv    = (const float*)d_in[1];
    const float* Wq    = (const float*)d_in[2];
    const float* Wk    = (const float*)d_in[3];
    const float* Wv    = (const float*)d_in[4];
    const float* Wo    = (const float*)d_in[5];
    const float* gamma = (const float*)d_in[6];
    const float* beta  = (const float*)d_in[7];
    const float* mean  = (const float*)d_in[8];
    const float* var   = (const float*)d_in[9];
    float* out = (float*)d_out;

    prep_pool<<<1536, 256>>>(Wq, Wk, Wv, Wo, query, kv);
    gemm_qkv<<<dim3(8, 2, 24), 256>>>();
    attn_kernel<<<dim3(8, 8, 8), 256>>>();
    gemm_o<<<dim3(16, 2, 8), 256>>>();
    final_kernel<<<8192, 256>>>(query, gamma, beta, mean, var, out);
}